// round 9
// baseline (speedup 1.0000x reference)
#include <cuda_runtime.h>
#include <math.h>

#define NN 100000
#define NE 1600000
#define NG 1000
#define NBLK 391   // ceil(NN/256)
#define SLOT 33
typedef unsigned long long ull;

// ---- scratch (static device globals; no allocation) ----
__device__ __align__(128) float g_posg[NN * 2];
__device__ __align__(128) float g_ncs [NN * 2];
__device__ __align__(128) float g_nacc[NN * 4];
__device__ __align__(128) float g_gacc[NG * 4];
__device__ int   g_deg[NN];
__device__ int   g_rowstart[NN];
__device__ int   g_cursor[NN];
__device__ int   g_psum[512];
__device__ __align__(128) float4 g_rec[NE];   // col(bits), s1*invd, c1, s1/invd
__device__ int   g_erow[NE];
__device__ __align__(128) float g_xs  [NN * 16];
__device__ __align__(128) float g_xrot[NN * 32];
__device__ __align__(128) float g_y   [NN * 32];
__device__ __align__(128) float g_as  [NN * 16];
__device__ __align__(128) float g_gate[NN * 16];
__device__ __align__(128) float g_aggR[NN * 32];
__device__ __align__(128) float g_aggS[NN * 16];

__device__ __forceinline__ void red4(float* a, float x, float y, float z, float w) {
    asm volatile("red.global.add.v4.f32 [%0], {%1,%2,%3,%4};"
                 :: "l"(a), "f"(x), "f"(y), "f"(z), "f"(w));
}
__device__ __forceinline__ void red1(float* a, float v) {
    asm volatile("red.global.add.f32 [%0], %1;" :: "l"(a), "f"(v));
}
__device__ __forceinline__ float lrelu(float x) { return x > 0.f ? x : 0.01f * x; }
__device__ __forceinline__ ull fma2(ull a, ull b, ull c) {
    ull d; asm("fma.rn.f32x2 %0,%1,%2,%3;" : "=l"(d) : "l"(a), "l"(b), "l"(c)); return d;
}
__device__ __forceinline__ ull pk2(float x, float y) {
    ull r; asm("mov.b64 %0,{%1,%2};" : "=l"(r) : "f"(x), "f"(y)); return r;
}
__device__ __forceinline__ float2 upk(ull v) {
    float2 r; asm("mov.b64 {%0,%1},%2;" : "=f"(r.x), "=f"(r.y) : "l"(v)); return r;
}

// ---- zero ----
__global__ void kZero(float* out) {
    int i = blockIdx.x * blockDim.x + threadIdx.x;
    for (int t = i; t < NN * 4; t += gridDim.x * blockDim.x) g_nacc[t] = 0.f;
    for (int t = i; t < NN; t += gridDim.x * blockDim.x) g_deg[t] = 0;
    if (i < NG * 4) g_gacc[i] = 0.f;
    if (i < NG * 6) out[i] = 0.f;
}

// edge-grid: per-edge degree histogram; first NN threads also do graph mean acc
__global__ void kGraphAcc(const float* __restrict__ pos, const int* __restrict__ batch,
                          const int* __restrict__ ei) {
    int n = blockIdx.x * blockDim.x + threadIdx.x;
    if (n < NN)
        red4(&g_gacc[batch[n] * 4], pos[2 * n], pos[2 * n + 1], 1.f, 0.f);
    if (n < NE)
        atomicAdd(&g_deg[ei[n]], 1);
}

// fused: center/rot (independent) + block-local scan of degrees
__global__ void kCenterScan(const float* __restrict__ pos, const int* __restrict__ batch) {
    __shared__ int s[256];
    int n = blockIdx.x * 256 + threadIdx.x;
    int v = (n < NN) ? g_deg[n] : 0;
    s[threadIdx.x] = v; __syncthreads();
    for (int d = 1; d < 256; d <<= 1) {
        int t = (threadIdx.x >= d) ? s[threadIdx.x - d] : 0;
        __syncthreads();
        s[threadIdx.x] += t;
        __syncthreads();
    }
    if (n < NN) g_rowstart[n] = s[threadIdx.x] - v;
    if (threadIdx.x == 255) g_psum[blockIdx.x] = s[255];
    if (n >= NN) return;
    float4 ga = *(const float4*)&g_gacc[batch[n] * 4];
    float inv = 1.f / fmaxf(ga.z, 1.f);
    float px = pos[2 * n]     - ga.x * inv;
    float py = pos[2 * n + 1] - ga.y * inv;
    g_posg[2 * n] = px; g_posg[2 * n + 1] = py;
    float r2 = px * px + py * py;
    float c = 1.f, sv = 0.f;
    if (r2 > 0.f) { float ir = rsqrtf(r2); c = px * ir; sv = py * ir; }
    g_ncs[2 * n] = c; g_ncs[2 * n + 1] = sv;
}

__global__ void kScanB() {
    __shared__ int s[512];
    int t = threadIdx.x;
    int v = (t < NBLK) ? g_psum[t] : 0;
    s[t] = v; __syncthreads();
    for (int d = 1; d < 512; d <<= 1) {
        int u = (t >= d) ? s[t - d] : 0;
        __syncthreads();
        s[t] += u;
        __syncthreads();
    }
    if (t < NBLK) g_psum[t] = s[t] - v;
}

__global__ void kScanC() {
    int n = blockIdx.x * 256 + threadIdx.x;
    if (n >= NN) return;
    int rs = g_rowstart[n] + g_psum[blockIdx.x];
    g_rowstart[n] = rs;
    g_cursor[n] = rs;
}

// ---- per-edge geometry + CSR fill ----
__global__ void kEdgeFill(const int* __restrict__ ei) {
    int e = blockIdx.x * blockDim.x + threadIdx.x;
    if (e >= NE) return;
    int r = ei[e], c = ei[NE + e];
    float vx = g_posg[2 * r] - g_posg[2 * c];
    float vy = g_posg[2 * r + 1] - g_posg[2 * c + 1];
    float r2 = vx * vx + vy * vy;
    float d = 0.f, cc = 1.f, ss = 0.f;
    if (r2 > 0.f) { float ir = rsqrtf(r2); d = r2 * ir; cc = vx * ir; ss = vy * ir; }
    float invd = 1.41421356237f / (d + 1e-8f);
    float s1, c1;
    sincosf(3.14159265358979f * d, &s1, &c1);
    int pos = atomicAdd(&g_cursor[r], 1);
    g_rec[pos] = make_float4(__int_as_float(c), s1 * invd, c1, s1 / invd);
    g_erow[pos] = r;
    red4(&g_nacc[r * 4], 1.f, d, cc, ss);
}

// ---- fused node kernel: post(prev) / init + pre(layer); zero agg ----
__global__ void kNodeFuse(const float* __restrict__ wse, const float* __restrict__ bse,
                          const float* __restrict__ Wemb,
                          const float* __restrict__ Wmix, const float* __restrict__ Wgate,
                          const float* __restrict__ bgate, const float* __restrict__ Ws1,
                          int layer) {
    __shared__ ull sMix2[256];            // Wmix[i][j] duplicated into both halves
    __shared__ ull sGate2[128], sWs2[128], sbg2[8];
    for (int t = threadIdx.x; t < 256; t += blockDim.x) {
        float w = Wmix[layer * 256 + t];
        sMix2[t] = pk2(w, w);
    }
    for (int t = threadIdx.x; t < 128; t += blockDim.x) {
        sGate2[t] = ((const ull*)(Wgate + layer * 256))[t];
        sWs2[t]   = ((const ull*)(Ws1 + layer * 512))[t];
    }
    if (threadIdx.x < 8) sbg2[threadIdx.x] = ((const ull*)(bgate + layer * 16))[threadIdx.x];
    __syncthreads();
    int n = blockIdx.x * blockDim.x + threadIdx.x;
    if (n >= NN) return;

    float xs[16], xr[32];
    if (layer == 0) {
        float4 a = *(const float4*)&g_nacc[n * 4];
        float deg = fmaxf(a.x, 1.f);
        float invdeg = 1.f / deg;
        float dmean = a.y * invdeg;
        float Cm = a.z * invdeg, Sm = a.w * invdeg;
#pragma unroll
        for (int i = 0; i < 16; i++) xs[i] = lrelu(dmean * wse[i] + bse[i]);
#pragma unroll
        for (int j = 0; j < 16; j++) {
            float w0 = Wemb[2 * j], w1 = Wemb[2 * j + 1];
            xr[2 * j]     = Cm * w0 - Sm * w1;
            xr[2 * j + 1] = Sm * w0 + Cm * w1;
        }
        g_nacc[n * 4] = invdeg;
        float4* po = (float4*)&g_xs[n * 16];
#pragma unroll
        for (int q = 0; q < 4; q++) po[q] = make_float4(xs[4*q], xs[4*q+1], xs[4*q+2], xs[4*q+3]);
        float4* pr = (float4*)&g_xrot[n * 32];
#pragma unroll
        for (int q = 0; q < 8; q++) pr[q] = make_float4(xr[4*q], xr[4*q+1], xr[4*q+2], xr[4*q+3]);
    } else {
        const float4* p = (const float4*)&g_xs[n * 16];
#pragma unroll
        for (int q = 0; q < 4; q++) { float4 v = p[q]; xs[4*q]=v.x; xs[4*q+1]=v.y; xs[4*q+2]=v.z; xs[4*q+3]=v.w; }
        const float4* pr = (const float4*)&g_xrot[n * 32];
#pragma unroll
        for (int q = 0; q < 8; q++) { float4 v = pr[q]; xr[4*q]=v.x; xr[4*q+1]=v.y; xr[4*q+2]=v.z; xr[4*q+3]=v.w; }
        float invd = g_nacc[n * 4];
#pragma unroll
        for (int j = 0; j < 16; j++) {
            float gt = g_gate[n * 16 + j] * invd;
            xr[2 * j]     += gt * g_aggR[n * 32 + 2 * j];
            xr[2 * j + 1] += gt * g_aggR[n * 32 + 2 * j + 1];
        }
#pragma unroll
        for (int i = 0; i < 16; i++) xs[i] += g_aggS[n * 16 + i] * invd;
        float4* po = (float4*)&g_xs[n * 16];
#pragma unroll
        for (int q = 0; q < 4; q++) po[q] = make_float4(xs[4*q], xs[4*q+1], xs[4*q+2], xs[4*q+3]);
        float4* pw = (float4*)&g_xrot[n * 32];
#pragma unroll
        for (int q = 0; q < 8; q++) pw[q] = make_float4(xr[4*q], xr[4*q+1], xr[4*q+2], xr[4*q+3]);
    }

    // y = Wmix @ x_rot  (packed)
    ull xr2[16];
#pragma unroll
    for (int j = 0; j < 16; j++) xr2[j] = pk2(xr[2 * j], xr[2 * j + 1]);
    ull* yo2 = (ull*)&g_y[n * 32];
#pragma unroll
    for (int i = 0; i < 16; i++) {
        ull acc = 0ull;
#pragma unroll
        for (int j = 0; j < 16; j++)
            acc = fma2(sMix2[i * 16 + j], xr2[j], acc);
        yo2[i] = acc;
    }
    ull gt2[8], as2[8];
#pragma unroll
    for (int i = 0; i < 8; i++) { gt2[i] = sbg2[i]; as2[i] = 0ull; }
#pragma unroll
    for (int k = 0; k < 16; k++) {
        ull xv2 = pk2(xs[k], xs[k]);
#pragma unroll
        for (int i = 0; i < 8; i++) {
            gt2[i] = fma2(xv2, sGate2[k * 8 + i], gt2[i]);
            as2[i] = fma2(xv2, sWs2[k * 8 + i], as2[i]);
        }
    }
#pragma unroll
    for (int i = 0; i < 8; i++) {
        float2 gv = upk(gt2[i]);
        g_gate[n * 16 + 2 * i]     = 1.f / (1.f + expf(-gv.x));
        g_gate[n * 16 + 2 * i + 1] = 1.f / (1.f + expf(-gv.y));
        ((ull*)&g_as[n * 16])[i] = as2[i];
    }
    // zero accumulators for this layer's edge pass
    float4 z = make_float4(0.f, 0.f, 0.f, 0.f);
    float4* ar = (float4*)&g_aggR[n * 32];
#pragma unroll
    for (int q = 0; q < 8; q++) ar[q] = z;
    float4* as4 = (float4*)&g_aggS[n * 16];
#pragma unroll
    for (int q = 0; q < 4; q++) as4[q] = z;
}

// ---- per-edge layer (hot): warp = 32 CSR edges; deep prefetched coalesced gathers ----
__global__ void __launch_bounds__(128) kEdgeLayerC(
                           const float* __restrict__ Wg, const float* __restrict__ bg,
                           const float* __restrict__ Ws1, const float* __restrict__ bs1,
                           int layer) {
    __shared__ ull sWg2[128], sWs2[128], sbg2[8], sbs2[8];
    __shared__ float smG[4][32 * SLOT];
    __shared__ int scol[4][32], srow[4][32];
    for (int t = threadIdx.x; t < 128; t += blockDim.x) {
        sWg2[t] = ((const ull*)(Wg + layer * 256))[t];
        sWs2[t] = ((const ull*)(Ws1 + layer * 512 + 256))[t];
    }
    if (threadIdx.x < 8) {
        sbg2[threadIdx.x] = ((const ull*)(bg + layer * 16))[threadIdx.x];
        sbs2[threadIdx.x] = ((const ull*)(bs1 + layer * 16))[threadIdx.x];
    }
    __syncthreads();
    int w = threadIdx.x >> 5;
    int lane = threadIdx.x & 31;
    int p = blockIdx.x * 128 + threadIdx.x;   // NE % 128 == 0

    // ---- phase 1: edge-parallel g/bs into smem ----
    {
        float4 rec = g_rec[p];
        scol[w][lane] = __float_as_int(rec.x);
        srow[w][lane] = g_erow[p];
        float s1p = rec.y, c1 = rec.z, t1 = rec.w;
        float emb[16];
        emb[0] = s1p;
        float sk = s1p, ck = c1;
#pragma unroll
        for (int k = 1; k < 16; k++) {
            float sn = fmaf(sk, c1,  ck * s1p);
            float cn = fmaf(ck, c1, -sk * t1);
            emb[k] = sn; sk = sn; ck = cn;
        }
        ull g2[8], b2[8];
#pragma unroll
        for (int i = 0; i < 8; i++) { g2[i] = sbg2[i]; b2[i] = sbs2[i]; }
#pragma unroll
        for (int k = 0; k < 16; k++) {
            ull dv2 = pk2(emb[k], emb[k]);
#pragma unroll
            for (int i = 0; i < 8; i++) {
                g2[i] = fma2(dv2, sWg2[k * 8 + i], g2[i]);
                b2[i] = fma2(dv2, sWs2[k * 8 + i], b2[i]);
            }
        }
        float* slot = &smG[w][lane * SLOT];
#pragma unroll
        for (int i = 0; i < 8; i++) {
            float2 gv = upk(g2[i]);
            slot[2 * i]     = gv.x;
            slot[2 * i + 1] = gv.y;
            float2 bv = upk(b2[i]);
            slot[16 + 2 * i]     = bv.x;
            slot[16 + 2 * i + 1] = bv.y;
        }
    }
    __syncwarp();

    // ---- phase 2: deep prefetch (all 32 y), av in halves, then ALU accumulate ----
    const float* smw = smG[w];
    const int* colw = scol[w];
    const int* roww = srow[w];
    int gidx = lane >> 1;
    bool sl = (lane < 16);
    float accR = 0.f, accS = 0.f;
    int cur = roww[0];

    float yv[32];
#pragma unroll
    for (int e = 0; e < 32; e++)
        yv[e] = g_y[(size_t)colw[e] * 32 + lane];
    float av[16];
#pragma unroll
    for (int e = 0; e < 16; e++)
        av[e] = sl ? g_as[(size_t)colw[e] * 16 + lane] : 0.f;
    // accumulate first half while av half-2 not yet needed
#pragma unroll
    for (int e = 0; e < 16; e++) {
        int r = roww[e];
        if (r != cur) {
            red1(&g_aggR[(size_t)cur * 32 + lane], accR);
            if (sl) red1(&g_aggS[(size_t)cur * 16 + lane], accS);
            accR = 0.f; accS = 0.f; cur = r;
        }
        float gv = smw[e * SLOT + gidx];
        accR = fmaf(gv, yv[e], accR);
        if (sl) accS += lrelu(av[e] + smw[e * SLOT + 16 + lane]);
    }
    // prefetch av half-2, accumulate second half
#pragma unroll
    for (int e = 0; e < 16; e++)
        av[e] = sl ? g_as[(size_t)colw[16 + e] * 16 + lane] : 0.f;
#pragma unroll
    for (int e = 16; e < 32; e++) {
        int r = roww[e];
        if (r != cur) {
            red1(&g_aggR[(size_t)cur * 32 + lane], accR);
            if (sl) red1(&g_aggS[(size_t)cur * 16 + lane], accS);
            accR = 0.f; accS = 0.f; cur = r;
        }
        float gv = smw[e * SLOT + gidx];
        accR = fmaf(gv, yv[e], accR);
        if (sl) accS += lrelu(av[e - 16] + smw[e * SLOT + 16 + lane]);
    }
    red1(&g_aggR[(size_t)cur * 32 + lane], accR);
    if (sl) red1(&g_aggS[(size_t)cur * 16 + lane], accS);
}

// ---- readout ----
__global__ void kOut(const float* __restrict__ W1, const float* __restrict__ b1,
                     const float* __restrict__ W2, const float* __restrict__ b2,
                     const int* __restrict__ batch, float* __restrict__ out) {
    __shared__ __align__(16) float sW1[48 * 144];
    __shared__ __align__(16) float sW2[144 * 6];
    __shared__ __align__(16) float sb1[144];
    __shared__ float sb2[6];
    for (int t = threadIdx.x; t < 48 * 144; t += blockDim.x) sW1[t] = W1[t];
    for (int t = threadIdx.x; t < 144 * 6; t += blockDim.x) sW2[t] = W2[t];
    for (int t = threadIdx.x; t < 144; t += blockDim.x) sb1[t] = b1[t];
    if (threadIdx.x < 6) sb2[threadIdx.x] = b2[threadIdx.x];
    __syncthreads();
    int n = blockIdx.x * blockDim.x + threadIdx.x;
    if (n >= NN) return;
    float invd = g_nacc[n * 4];
    float xc[48];
#pragma unroll
    for (int i = 0; i < 16; i++)
        xc[i] = g_xs[n * 16 + i] + g_aggS[n * 16 + i] * invd;
    float cc = g_ncs[2 * n], ss = g_ncs[2 * n + 1];
#pragma unroll
    for (int j = 0; j < 16; j++) {
        float gt = g_gate[n * 16 + j] * invd;
        float x0 = g_xrot[n * 32 + 2 * j]     + gt * g_aggR[n * 32 + 2 * j];
        float x1 = g_xrot[n * 32 + 2 * j + 1] + gt * g_aggR[n * 32 + 2 * j + 1];
        xc[16 + 2 * j]     = cc * x0 - ss * x1;
        xc[16 + 2 * j + 1] = ss * x0 + cc * x1;
    }
    float u[6];
#pragma unroll
    for (int q = 0; q < 6; q++) u[q] = sb2[q];
    for (int o = 0; o < 144; o += 4) {
        float4 h = *(const float4*)&sb1[o];
#pragma unroll
        for (int k = 0; k < 48; k++) {
            float4 w = *(const float4*)&sW1[k * 144 + o];
            float xv = xc[k];
            h.x = fmaf(xv, w.x, h.x);
            h.y = fmaf(xv, w.y, h.y);
            h.z = fmaf(xv, w.z, h.z);
            h.w = fmaf(xv, w.w, h.w);
        }
        h.x = lrelu(h.x); h.y = lrelu(h.y); h.z = lrelu(h.z); h.w = lrelu(h.w);
        float hv[4] = {h.x, h.y, h.z, h.w};
#pragma unroll
        for (int j = 0; j < 4; j++)
#pragma unroll
            for (int q = 0; q < 6; q++)
                u[q] = fmaf(hv[j], sW2[(o + j) * 6 + q], u[q]);
    }
    int b = batch[n];
#pragma unroll
    for (int q = 0; q < 6; q++) atomicAdd(&out[b * 6 + q], u[q]);
}

extern "C" void kernel_launch(void* const* d_in, const int* in_sizes, int n_in,
                              void* d_out, int out_size) {
    const float* pos   = (const float*)d_in[0];
    const float* Wemb  = (const float*)d_in[1];
    const float* wse   = (const float*)d_in[2];
    const float* bse   = (const float*)d_in[3];
    const float* Wg    = (const float*)d_in[4];
    const float* bg    = (const float*)d_in[5];
    const float* Wmix  = (const float*)d_in[6];
    const float* Wgate = (const float*)d_in[7];
    const float* bgate = (const float*)d_in[8];
    const float* Ws1   = (const float*)d_in[9];
    const float* bs1   = (const float*)d_in[10];
    const float* W1    = (const float*)d_in[11];
    const float* b1    = (const float*)d_in[12];
    const float* W2    = (const float*)d_in[13];
    const float* b2    = (const float*)d_in[14];
    const int*   ei    = (const int*)d_in[15];
    const int*   batch = (const int*)d_in[16];
    float* out = (float*)d_out;

    int nb = (NN + 255) / 256;
    int eb = (NE + 255) / 256;

    kZero<<<1563, 256>>>(out);
    kGraphAcc<<<eb, 256>>>(pos, batch, ei);
    kCenterScan<<<NBLK, 256>>>(pos, batch);
    kScanB<<<1, 512>>>();
    kScanC<<<NBLK, 256>>>();
    kEdgeFill<<<eb, 256>>>(ei);
    for (int l = 0; l < 3; l++) {
        kNodeFuse<<<nb, 256>>>(wse, bse, Wemb, Wmix, Wgate, bgate, Ws1, l);
        kEdgeLayerC<<<NE / 128, 128>>>(Wg, bg, Ws1, bs1, l);
    }
    kOut<<<(NN + 127) / 128, 128>>>(W1, b1, W2, b2, batch, out);
}

// round 10
// speedup vs baseline: 1.0690x; 1.0690x over previous
#include <cuda_runtime.h>
#include <math.h>

#define NN 100000
#define NE 1600000
#define NG 1000
#define NBLK 391   // ceil(NN/256)
#define SLOT 33
typedef unsigned long long ull;

// ---- scratch (static device globals; no allocation) ----
__device__ __align__(128) float g_posg[NN * 2];
__device__ __align__(128) float g_ncs [NN * 2];
__device__ __align__(128) float g_nacc[NN * 4];
__device__ __align__(128) float g_gacc[NG * 4];
__device__ int   g_deg[NN];
__device__ int   g_rowstart[NN];
__device__ int   g_cursor[NN];
__device__ int   g_psum[512];
__device__ __align__(128) float4 g_rec[NE];   // col(bits), s1*invd, c1, s1/invd
__device__ int   g_erow[NE];
__device__ __align__(128) float g_xs  [NN * 16];
__device__ __align__(128) float g_xrot[NN * 32];
__device__ __align__(128) float g_y   [NN * 32];
__device__ __align__(128) float g_as  [NN * 16];
__device__ __align__(128) float g_gate[NN * 16];
__device__ __align__(128) float g_aggR[NN * 32];
__device__ __align__(128) float g_aggS[NN * 16];

__device__ __forceinline__ void red4(float* a, float x, float y, float z, float w) {
    asm volatile("red.global.add.v4.f32 [%0], {%1,%2,%3,%4};"
                 :: "l"(a), "f"(x), "f"(y), "f"(z), "f"(w));
}
__device__ __forceinline__ void red1(float* a, float v) {
    asm volatile("red.global.add.f32 [%0], %1;" :: "l"(a), "f"(v));
}
__device__ __forceinline__ float lrelu(float x) { return x > 0.f ? x : 0.01f * x; }
__device__ __forceinline__ ull fma2(ull a, ull b, ull c) {
    ull d; asm("fma.rn.f32x2 %0,%1,%2,%3;" : "=l"(d) : "l"(a), "l"(b), "l"(c)); return d;
}
__device__ __forceinline__ ull pk2(float x, float y) {
    ull r; asm("mov.b64 %0,{%1,%2};" : "=l"(r) : "f"(x), "f"(y)); return r;
}
__device__ __forceinline__ float2 upk(ull v) {
    float2 r; asm("mov.b64 {%0,%1},%2;" : "=f"(r.x), "=f"(r.y) : "l"(v)); return r;
}

// ---- zero ----
__global__ void kZero(float* out) {
    int i = blockIdx.x * blockDim.x + threadIdx.x;
    for (int t = i; t < NN * 4; t += gridDim.x * blockDim.x) g_nacc[t] = 0.f;
    for (int t = i; t < NN; t += gridDim.x * blockDim.x) g_deg[t] = 0;
    if (i < NG * 4) g_gacc[i] = 0.f;
    if (i < NG * 6) out[i] = 0.f;
}

// edge-grid: per-edge degree histogram; first NN threads also do graph mean acc
__global__ void kGraphAcc(const float* __restrict__ pos, const int* __restrict__ batch,
                          const int* __restrict__ ei) {
    int n = blockIdx.x * blockDim.x + threadIdx.x;
    if (n < NN)
        red4(&g_gacc[batch[n] * 4], pos[2 * n], pos[2 * n + 1], 1.f, 0.f);
    if (n < NE)
        atomicAdd(&g_deg[ei[n]], 1);
}

// fused: center/rot (independent) + block-local scan of degrees
__global__ void kCenterScan(const float* __restrict__ pos, const int* __restrict__ batch) {
    __shared__ int s[256];
    int n = blockIdx.x * 256 + threadIdx.x;
    int v = (n < NN) ? g_deg[n] : 0;
    s[threadIdx.x] = v; __syncthreads();
    for (int d = 1; d < 256; d <<= 1) {
        int t = (threadIdx.x >= d) ? s[threadIdx.x - d] : 0;
        __syncthreads();
        s[threadIdx.x] += t;
        __syncthreads();
    }
    if (n < NN) g_rowstart[n] = s[threadIdx.x] - v;
    if (threadIdx.x == 255) g_psum[blockIdx.x] = s[255];
    if (n >= NN) return;
    float4 ga = *(const float4*)&g_gacc[batch[n] * 4];
    float inv = 1.f / fmaxf(ga.z, 1.f);
    float px = pos[2 * n]     - ga.x * inv;
    float py = pos[2 * n + 1] - ga.y * inv;
    g_posg[2 * n] = px; g_posg[2 * n + 1] = py;
    float r2 = px * px + py * py;
    float c = 1.f, sv = 0.f;
    if (r2 > 0.f) { float ir = rsqrtf(r2); c = px * ir; sv = py * ir; }
    g_ncs[2 * n] = c; g_ncs[2 * n + 1] = sv;
}

__global__ void kScanB() {
    __shared__ int s[512];
    int t = threadIdx.x;
    int v = (t < NBLK) ? g_psum[t] : 0;
    s[t] = v; __syncthreads();
    for (int d = 1; d < 512; d <<= 1) {
        int u = (t >= d) ? s[t - d] : 0;
        __syncthreads();
        s[t] += u;
        __syncthreads();
    }
    if (t < NBLK) g_psum[t] = s[t] - v;
}

__global__ void kScanC() {
    int n = blockIdx.x * 256 + threadIdx.x;
    if (n >= NN) return;
    int rs = g_rowstart[n] + g_psum[blockIdx.x];
    g_rowstart[n] = rs;
    g_cursor[n] = rs;
}

// ---- per-edge geometry + CSR fill ----
__global__ void kEdgeFill(const int* __restrict__ ei) {
    int e = blockIdx.x * blockDim.x + threadIdx.x;
    if (e >= NE) return;
    int r = ei[e], c = ei[NE + e];
    float vx = g_posg[2 * r] - g_posg[2 * c];
    float vy = g_posg[2 * r + 1] - g_posg[2 * c + 1];
    float r2 = vx * vx + vy * vy;
    float d = 0.f, cc = 1.f, ss = 0.f;
    if (r2 > 0.f) { float ir = rsqrtf(r2); d = r2 * ir; cc = vx * ir; ss = vy * ir; }
    float invd = 1.41421356237f / (d + 1e-8f);
    float s1, c1;
    __sincosf(3.14159265358979f * d, &s1, &c1);
    int pos = atomicAdd(&g_cursor[r], 1);
    g_rec[pos] = make_float4(__int_as_float(c), s1 * invd, c1, s1 / invd);
    g_erow[pos] = r;
    red4(&g_nacc[r * 4], 1.f, d, cc, ss);
}

// ---- fused node kernel: post(prev) / init + pre(layer); zero agg ----
__global__ void kNodeFuse(const float* __restrict__ wse, const float* __restrict__ bse,
                          const float* __restrict__ Wemb,
                          const float* __restrict__ Wmix, const float* __restrict__ Wgate,
                          const float* __restrict__ bgate, const float* __restrict__ Ws1,
                          int layer) {
    __shared__ ull sMix2[256];            // Wmix[i][j] duplicated into both halves
    __shared__ ull sGate2[128], sWs2[128], sbg2[8];
    for (int t = threadIdx.x; t < 256; t += blockDim.x) {
        float w = Wmix[layer * 256 + t];
        sMix2[t] = pk2(w, w);
    }
    for (int t = threadIdx.x; t < 128; t += blockDim.x) {
        sGate2[t] = ((const ull*)(Wgate + layer * 256))[t];
        sWs2[t]   = ((const ull*)(Ws1 + layer * 512))[t];
    }
    if (threadIdx.x < 8) sbg2[threadIdx.x] = ((const ull*)(bgate + layer * 16))[threadIdx.x];
    __syncthreads();
    int n = blockIdx.x * blockDim.x + threadIdx.x;
    if (n >= NN) return;

    float xs[16], xr[32];
    if (layer == 0) {
        float4 a = *(const float4*)&g_nacc[n * 4];
        float deg = fmaxf(a.x, 1.f);
        float invdeg = 1.f / deg;
        float dmean = a.y * invdeg;
        float Cm = a.z * invdeg, Sm = a.w * invdeg;
#pragma unroll
        for (int i = 0; i < 16; i++) xs[i] = lrelu(dmean * wse[i] + bse[i]);
#pragma unroll
        for (int j = 0; j < 16; j++) {
            float w0 = Wemb[2 * j], w1 = Wemb[2 * j + 1];
            xr[2 * j]     = Cm * w0 - Sm * w1;
            xr[2 * j + 1] = Sm * w0 + Cm * w1;
        }
        g_nacc[n * 4] = invdeg;
        float4* po = (float4*)&g_xs[n * 16];
#pragma unroll
        for (int q = 0; q < 4; q++) po[q] = make_float4(xs[4*q], xs[4*q+1], xs[4*q+2], xs[4*q+3]);
        float4* pr = (float4*)&g_xrot[n * 32];
#pragma unroll
        for (int q = 0; q < 8; q++) pr[q] = make_float4(xr[4*q], xr[4*q+1], xr[4*q+2], xr[4*q+3]);
    } else {
        const float4* p = (const float4*)&g_xs[n * 16];
#pragma unroll
        for (int q = 0; q < 4; q++) { float4 v = p[q]; xs[4*q]=v.x; xs[4*q+1]=v.y; xs[4*q+2]=v.z; xs[4*q+3]=v.w; }
        const float4* pr = (const float4*)&g_xrot[n * 32];
#pragma unroll
        for (int q = 0; q < 8; q++) { float4 v = pr[q]; xr[4*q]=v.x; xr[4*q+1]=v.y; xr[4*q+2]=v.z; xr[4*q+3]=v.w; }
        float invd = g_nacc[n * 4];
#pragma unroll
        for (int j = 0; j < 16; j++) {
            float gt = g_gate[n * 16 + j] * invd;
            xr[2 * j]     += gt * g_aggR[n * 32 + 2 * j];
            xr[2 * j + 1] += gt * g_aggR[n * 32 + 2 * j + 1];
        }
#pragma unroll
        for (int i = 0; i < 16; i++) xs[i] += g_aggS[n * 16 + i] * invd;
        float4* po = (float4*)&g_xs[n * 16];
#pragma unroll
        for (int q = 0; q < 4; q++) po[q] = make_float4(xs[4*q], xs[4*q+1], xs[4*q+2], xs[4*q+3]);
        float4* pw = (float4*)&g_xrot[n * 32];
#pragma unroll
        for (int q = 0; q < 8; q++) pw[q] = make_float4(xr[4*q], xr[4*q+1], xr[4*q+2], xr[4*q+3]);
    }

    // y = Wmix @ x_rot  (packed)
    ull xr2[16];
#pragma unroll
    for (int j = 0; j < 16; j++) xr2[j] = pk2(xr[2 * j], xr[2 * j + 1]);
    ull* yo2 = (ull*)&g_y[n * 32];
#pragma unroll
    for (int i = 0; i < 16; i++) {
        ull acc = 0ull;
#pragma unroll
        for (int j = 0; j < 16; j++)
            acc = fma2(sMix2[i * 16 + j], xr2[j], acc);
        yo2[i] = acc;
    }
    ull gt2[8], as2[8];
#pragma unroll
    for (int i = 0; i < 8; i++) { gt2[i] = sbg2[i]; as2[i] = 0ull; }
#pragma unroll
    for (int k = 0; k < 16; k++) {
        ull xv2 = pk2(xs[k], xs[k]);
#pragma unroll
        for (int i = 0; i < 8; i++) {
            gt2[i] = fma2(xv2, sGate2[k * 8 + i], gt2[i]);
            as2[i] = fma2(xv2, sWs2[k * 8 + i], as2[i]);
        }
    }
#pragma unroll
    for (int i = 0; i < 8; i++) {
        float2 gv = upk(gt2[i]);
        g_gate[n * 16 + 2 * i]     = 1.f / (1.f + expf(-gv.x));
        g_gate[n * 16 + 2 * i + 1] = 1.f / (1.f + expf(-gv.y));
        ((ull*)&g_as[n * 16])[i] = as2[i];
    }
    // zero accumulators for this layer's edge pass
    float4 z = make_float4(0.f, 0.f, 0.f, 0.f);
    float4* ar = (float4*)&g_aggR[n * 32];
#pragma unroll
    for (int q = 0; q < 8; q++) ar[q] = z;
    float4* as4 = (float4*)&g_aggS[n * 16];
#pragma unroll
    for (int q = 0; q < 4; q++) as4[q] = z;
}

// ---- per-edge layer (hot): warp = 32 CSR edges; prefetched coalesced gathers (R8 structure) ----
__global__ void __launch_bounds__(128) kEdgeLayerC(
                           const float* __restrict__ Wg, const float* __restrict__ bg,
                           const float* __restrict__ Ws1, const float* __restrict__ bs1,
                           int layer) {
    __shared__ ull sWg2[128], sWs2[128], sbg2[8], sbs2[8];
    __shared__ float smG[4][32 * SLOT];
    __shared__ int scol[4][32], srow[4][32];
    for (int t = threadIdx.x; t < 128; t += blockDim.x) {
        sWg2[t] = ((const ull*)(Wg + layer * 256))[t];
        sWs2[t] = ((const ull*)(Ws1 + layer * 512 + 256))[t];
    }
    if (threadIdx.x < 8) {
        sbg2[threadIdx.x] = ((const ull*)(bg + layer * 16))[threadIdx.x];
        sbs2[threadIdx.x] = ((const ull*)(bs1 + layer * 16))[threadIdx.x];
    }
    __syncthreads();
    int w = threadIdx.x >> 5;
    int lane = threadIdx.x & 31;
    int p = blockIdx.x * 128 + threadIdx.x;   // NE % 128 == 0

    // ---- phase 1: edge-parallel g/bs into smem ----
    {
        float4 rec = g_rec[p];
        scol[w][lane] = __float_as_int(rec.x);
        srow[w][lane] = g_erow[p];
        float s1p = rec.y, c1 = rec.z, t1 = rec.w;
        float emb[16];
        emb[0] = s1p;
        float sk = s1p, ck = c1;
#pragma unroll
        for (int k = 1; k < 16; k++) {
            float sn = fmaf(sk, c1,  ck * s1p);
            float cn = fmaf(ck, c1, -sk * t1);
            emb[k] = sn; sk = sn; ck = cn;
        }
        ull g2[8], b2[8];
#pragma unroll
        for (int i = 0; i < 8; i++) { g2[i] = sbg2[i]; b2[i] = sbs2[i]; }
#pragma unroll
        for (int k = 0; k < 16; k++) {
            ull dv2 = pk2(emb[k], emb[k]);
#pragma unroll
            for (int i = 0; i < 8; i++) {
                g2[i] = fma2(dv2, sWg2[k * 8 + i], g2[i]);
                b2[i] = fma2(dv2, sWs2[k * 8 + i], b2[i]);
            }
        }
        float* slot = &smG[w][lane * SLOT];
#pragma unroll
        for (int i = 0; i < 8; i++) {
            float2 gv = upk(g2[i]);
            slot[2 * i]     = gv.x;
            slot[2 * i + 1] = gv.y;
            float2 bv = upk(b2[i]);
            slot[16 + 2 * i]     = bv.x;
            slot[16 + 2 * i + 1] = bv.y;
        }
    }
    __syncwarp();

    // ---- phase 2: two 16-edge batches; branch-free prefetch then ALU accumulate ----
    const float* smw = smG[w];
    const int* colw = scol[w];
    const int* roww = srow[w];
    int gidx = lane >> 1;
    bool sl = (lane < 16);
    float accR = 0.f, accS = 0.f;
    int cur = roww[0];
#pragma unroll
    for (int half = 0; half < 2; half++) {
        int base = half * 16;
        float yv[16], av[16];
#pragma unroll
        for (int e = 0; e < 16; e++) {
            int c = colw[base + e];
            yv[e] = g_y[(size_t)c * 32 + lane];
            av[e] = sl ? g_as[(size_t)c * 16 + lane] : 0.f;
        }
#pragma unroll
        for (int e = 0; e < 16; e++) {
            int idx = base + e;
            int r = roww[idx];
            if (r != cur) {
                red1(&g_aggR[(size_t)cur * 32 + lane], accR);
                if (sl) red1(&g_aggS[(size_t)cur * 16 + lane], accS);
                accR = 0.f; accS = 0.f; cur = r;
            }
            float gv = smw[idx * SLOT + gidx];
            accR = fmaf(gv, yv[e], accR);
            if (sl) accS += lrelu(av[e] + smw[idx * SLOT + 16 + lane]);
        }
    }
    red1(&g_aggR[(size_t)cur * 32 + lane], accR);
    if (sl) red1(&g_aggS[(size_t)cur * 16 + lane], accS);
}

// ---- readout: final post + rotate out + 48->144->6 MLP (f32x2 packed) + graph scatter ----
__global__ void kOut(const float* __restrict__ W1, const float* __restrict__ b1,
                     const float* __restrict__ W2, const float* __restrict__ b2,
                     const int* __restrict__ batch, float* __restrict__ out) {
    __shared__ __align__(16) float sW1[48 * 144];
    __shared__ __align__(16) float sW2[144 * 6];
    __shared__ __align__(16) float sb1[144];
    __shared__ float sb2[8];
    for (int t = threadIdx.x; t < 48 * 144; t += blockDim.x) sW1[t] = W1[t];
    for (int t = threadIdx.x; t < 144 * 6; t += blockDim.x) sW2[t] = W2[t];
    for (int t = threadIdx.x; t < 144; t += blockDim.x) sb1[t] = b1[t];
    if (threadIdx.x < 6) sb2[threadIdx.x] = b2[threadIdx.x];
    if (threadIdx.x >= 6 && threadIdx.x < 8) sb2[threadIdx.x] = 0.f;
    __syncthreads();
    int n = blockIdx.x * blockDim.x + threadIdx.x;
    if (n >= NN) return;
    float invd = g_nacc[n * 4];
    float xc[48];
#pragma unroll
    for (int i = 0; i < 16; i++)
        xc[i] = g_xs[n * 16 + i] + g_aggS[n * 16 + i] * invd;
    float cc = g_ncs[2 * n], ss = g_ncs[2 * n + 1];
#pragma unroll
    for (int j = 0; j < 16; j++) {
        float gt = g_gate[n * 16 + j] * invd;
        float x0 = g_xrot[n * 32 + 2 * j]     + gt * g_aggR[n * 32 + 2 * j];
        float x1 = g_xrot[n * 32 + 2 * j + 1] + gt * g_aggR[n * 32 + 2 * j + 1];
        xc[16 + 2 * j]     = cc * x0 - ss * x1;
        xc[16 + 2 * j + 1] = ss * x0 + cc * x1;
    }
    // u accumulators as 3 packed pairs
    ull u2[3];
    u2[0] = pk2(sb2[0], sb2[1]);
    u2[1] = pk2(sb2[2], sb2[3]);
    u2[2] = pk2(sb2[4], sb2[5]);
    for (int o = 0; o < 144; o += 4) {
        const ull* wb = (const ull*)&sb1[o];
        ull h01 = wb[0], h23 = wb[1];
#pragma unroll
        for (int k = 0; k < 48; k++) {
            const ull* wp = (const ull*)&sW1[k * 144 + o];
            ull xv2 = pk2(xc[k], xc[k]);
            h01 = fma2(xv2, wp[0], h01);
            h23 = fma2(xv2, wp[1], h23);
        }
        float2 ha = upk(h01), hb = upk(h23);
        float hv[4] = {lrelu(ha.x), lrelu(ha.y), lrelu(hb.x), lrelu(hb.y)};
#pragma unroll
        for (int j = 0; j < 4; j++) {
            ull hj2 = pk2(hv[j], hv[j]);
            const ull* w2p = (const ull*)&sW2[(o + j) * 6];
            u2[0] = fma2(hj2, w2p[0], u2[0]);
            u2[1] = fma2(hj2, w2p[1], u2[1]);
            u2[2] = fma2(hj2, w2p[2], u2[2]);
        }
    }
    int b = batch[n];
    float2 ua = upk(u2[0]), ub = upk(u2[1]), uc = upk(u2[2]);
    atomicAdd(&out[b * 6 + 0], ua.x);
    atomicAdd(&out[b * 6 + 1], ua.y);
    atomicAdd(&out[b * 6 + 2], ub.x);
    atomicAdd(&out[b * 6 + 3], ub.y);
    atomicAdd(&out[b * 6 + 4], uc.x);
    atomicAdd(&out[b * 6 + 5], uc.y);
}

extern "C" void kernel_launch(void* const* d_in, const int* in_sizes, int n_in,
                              void* d_out, int out_size) {
    const float* pos   = (const float*)d_in[0];
    const float* Wemb  = (const float*)d_in[1];
    const float* wse   = (const float*)d_in[2];
    const float* bse   = (const float*)d_in[3];
    const float* Wg    = (const float*)d_in[4];
    const float* bg    = (const float*)d_in[5];
    const float* Wmix  = (const float*)d_in[6];
    const float* Wgate = (const float*)d_in[7];
    const float* bgate = (const float*)d_in[8];
    const float* Ws1   = (const float*)d_in[9];
    const float* bs1   = (const float*)d_in[10];
    const float* W1    = (const float*)d_in[11];
    const float* b1    = (const float*)d_in[12];
    const float* W2    = (const float*)d_in[13];
    const float* b2    = (const float*)d_in[14];
    const int*   ei    = (const int*)d_in[15];
    const int*   batch = (const int*)d_in[16];
    float* out = (float*)d_out;

    int nb = (NN + 255) / 256;
    int eb = (NE + 255) / 256;

    kZero<<<1563, 256>>>(out);
    kGraphAcc<<<eb, 256>>>(pos, batch, ei);
    kCenterScan<<<NBLK, 256>>>(pos, batch);
    kScanB<<<1, 512>>>();
    kScanC<<<NBLK, 256>>>();
    kEdgeFill<<<eb, 256>>>(ei);
    for (int l = 0; l < 3; l++) {
        kNodeFuse<<<nb, 256>>>(wse, bse, Wemb, Wmix, Wgate, bgate, Ws1, l);
        kEdgeLayerC<<<NE / 128, 128>>>(Wg, bg, Ws1, bs1, l);
    }
    kOut<<<(NN + 127) / 128, 128>>>(W1, b1, W2, b2, batch, out);
}

// round 11
// speedup vs baseline: 1.0883x; 1.0180x over previous
#include <cuda_runtime.h>
#include <math.h>

#define NN 100000
#define NE 1600000
#define NG 1000
#define NBLK 391   // ceil(NN/256)
#define SLOT 33
typedef unsigned long long ull;

// ---- scratch (static device globals; no allocation) ----
__device__ __align__(128) float g_posg[NN * 2];
__device__ __align__(128) float g_ncs [NN * 2];
__device__ __align__(128) float g_nacc[NN * 4];
__device__ __align__(128) float g_gacc[NG * 4];
__device__ int   g_deg[NN];
__device__ int   g_rowstart[NN];
__device__ int   g_cursor[NN];
__device__ int   g_psum[512];
__device__ __align__(128) float4 g_rec[NE];   // col(bits), s1*invd, c1, s1/invd
__device__ int   g_erow[NE];
__device__ __align__(128) float g_xs  [NN * 16];
__device__ __align__(128) float g_xrot[NN * 32];
__device__ __align__(128) float g_y   [NN * 32];
__device__ __align__(128) float g_as  [NN * 16];
__device__ __align__(128) float g_gate[NN * 16];
__device__ __align__(128) float g_aggR[NN * 32];
__device__ __align__(128) float g_aggS[NN * 16];

__device__ __forceinline__ void red4(float* a, float x, float y, float z, float w) {
    asm volatile("red.global.add.v4.f32 [%0], {%1,%2,%3,%4};"
                 :: "l"(a), "f"(x), "f"(y), "f"(z), "f"(w));
}
__device__ __forceinline__ void red1(float* a, float v) {
    asm volatile("red.global.add.f32 [%0], %1;" :: "l"(a), "f"(v));
}
__device__ __forceinline__ float lrelu(float x) { return x > 0.f ? x : 0.01f * x; }
__device__ __forceinline__ ull fma2(ull a, ull b, ull c) {
    ull d; asm("fma.rn.f32x2 %0,%1,%2,%3;" : "=l"(d) : "l"(a), "l"(b), "l"(c)); return d;
}
__device__ __forceinline__ ull pk2(float x, float y) {
    ull r; asm("mov.b64 %0,{%1,%2};" : "=l"(r) : "f"(x), "f"(y)); return r;
}
__device__ __forceinline__ float2 upk(ull v) {
    float2 r; asm("mov.b64 {%0,%1},%2;" : "=f"(r.x), "=f"(r.y) : "l"(v)); return r;
}

// ---- zero ----
__global__ void kZero(float* out) {
    int i = blockIdx.x * blockDim.x + threadIdx.x;
    for (int t = i; t < NN * 4; t += gridDim.x * blockDim.x) g_nacc[t] = 0.f;
    for (int t = i; t < NN; t += gridDim.x * blockDim.x) g_deg[t] = 0;
    if (i < NG * 4) g_gacc[i] = 0.f;
    if (i < NG * 6) out[i] = 0.f;
}

// edge-grid: per-edge degree histogram; first NN threads also do graph mean acc
__global__ void kGraphAcc(const float* __restrict__ pos, const int* __restrict__ batch,
                          const int* __restrict__ ei) {
    int n = blockIdx.x * blockDim.x + threadIdx.x;
    if (n < NN)
        red4(&g_gacc[batch[n] * 4], pos[2 * n], pos[2 * n + 1], 1.f, 0.f);
    if (n < NE)
        atomicAdd(&g_deg[ei[n]], 1);
}

// fused: center/rot (independent) + block-local scan of degrees
__global__ void kCenterScan(const float* __restrict__ pos, const int* __restrict__ batch) {
    __shared__ int s[256];
    int n = blockIdx.x * 256 + threadIdx.x;
    int v = (n < NN) ? g_deg[n] : 0;
    s[threadIdx.x] = v; __syncthreads();
    for (int d = 1; d < 256; d <<= 1) {
        int t = (threadIdx.x >= d) ? s[threadIdx.x - d] : 0;
        __syncthreads();
        s[threadIdx.x] += t;
        __syncthreads();
    }
    if (n < NN) g_rowstart[n] = s[threadIdx.x] - v;
    if (threadIdx.x == 255) g_psum[blockIdx.x] = s[255];
    if (n >= NN) return;
    float4 ga = *(const float4*)&g_gacc[batch[n] * 4];
    float inv = 1.f / fmaxf(ga.z, 1.f);
    float px = pos[2 * n]     - ga.x * inv;
    float py = pos[2 * n + 1] - ga.y * inv;
    g_posg[2 * n] = px; g_posg[2 * n + 1] = py;
    float r2 = px * px + py * py;
    float c = 1.f, sv = 0.f;
    if (r2 > 0.f) { float ir = rsqrtf(r2); c = px * ir; sv = py * ir; }
    g_ncs[2 * n] = c; g_ncs[2 * n + 1] = sv;
}

__global__ void kScanB() {
    __shared__ int s[512];
    int t = threadIdx.x;
    int v = (t < NBLK) ? g_psum[t] : 0;
    s[t] = v; __syncthreads();
    for (int d = 1; d < 512; d <<= 1) {
        int u = (t >= d) ? s[t - d] : 0;
        __syncthreads();
        s[t] += u;
        __syncthreads();
    }
    if (t < NBLK) g_psum[t] = s[t] - v;
}

__global__ void kScanC() {
    int n = blockIdx.x * 256 + threadIdx.x;
    if (n >= NN) return;
    int rs = g_rowstart[n] + g_psum[blockIdx.x];
    g_rowstart[n] = rs;
    g_cursor[n] = rs;
}

// ---- per-edge geometry + CSR fill ----
__global__ void kEdgeFill(const int* __restrict__ ei) {
    int e = blockIdx.x * blockDim.x + threadIdx.x;
    if (e >= NE) return;
    int r = ei[e], c = ei[NE + e];
    float vx = g_posg[2 * r] - g_posg[2 * c];
    float vy = g_posg[2 * r + 1] - g_posg[2 * c + 1];
    float r2 = vx * vx + vy * vy;
    float d = 0.f, cc = 1.f, ss = 0.f;
    if (r2 > 0.f) { float ir = rsqrtf(r2); d = r2 * ir; cc = vx * ir; ss = vy * ir; }
    float invd = 1.41421356237f / (d + 1e-8f);
    float s1, c1;
    __sincosf(3.14159265358979f * d, &s1, &c1);
    int pos = atomicAdd(&g_cursor[r], 1);
    g_rec[pos] = make_float4(__int_as_float(c), s1 * invd, c1, s1 / invd);
    g_erow[pos] = r;
    red4(&g_nacc[r * 4], 1.f, d, cc, ss);
}

// ---- fused node kernel: post(prev) / init + pre(layer); zero agg ----
__global__ void kNodeFuse(const float* __restrict__ wse, const float* __restrict__ bse,
                          const float* __restrict__ Wemb,
                          const float* __restrict__ Wmix, const float* __restrict__ Wgate,
                          const float* __restrict__ bgate, const float* __restrict__ Ws1,
                          int layer) {
    __shared__ __align__(16) ull sMix2[256];   // Wmix[i][j] duplicated into both halves
    __shared__ __align__(16) ull sGate2[128], sWs2[128];
    __shared__ ull sbg2[8];
    for (int t = threadIdx.x; t < 256; t += blockDim.x) {
        float w = Wmix[layer * 256 + t];
        sMix2[t] = pk2(w, w);
    }
    for (int t = threadIdx.x; t < 128; t += blockDim.x) {
        sGate2[t] = ((const ull*)(Wgate + layer * 256))[t];
        sWs2[t]   = ((const ull*)(Ws1 + layer * 512))[t];
    }
    if (threadIdx.x < 8) sbg2[threadIdx.x] = ((const ull*)(bgate + layer * 16))[threadIdx.x];
    __syncthreads();
    int n = blockIdx.x * blockDim.x + threadIdx.x;
    if (n >= NN) return;

    float xs[16], xr[32];
    if (layer == 0) {
        float4 a = *(const float4*)&g_nacc[n * 4];
        float deg = fmaxf(a.x, 1.f);
        float invdeg = 1.f / deg;
        float dmean = a.y * invdeg;
        float Cm = a.z * invdeg, Sm = a.w * invdeg;
#pragma unroll
        for (int i = 0; i < 16; i++) xs[i] = lrelu(dmean * wse[i] + bse[i]);
#pragma unroll
        for (int j = 0; j < 16; j++) {
            float w0 = Wemb[2 * j], w1 = Wemb[2 * j + 1];
            xr[2 * j]     = Cm * w0 - Sm * w1;
            xr[2 * j + 1] = Sm * w0 + Cm * w1;
        }
        g_nacc[n * 4] = invdeg;
        float4* po = (float4*)&g_xs[n * 16];
#pragma unroll
        for (int q = 0; q < 4; q++) po[q] = make_float4(xs[4*q], xs[4*q+1], xs[4*q+2], xs[4*q+3]);
        float4* pr = (float4*)&g_xrot[n * 32];
#pragma unroll
        for (int q = 0; q < 8; q++) pr[q] = make_float4(xr[4*q], xr[4*q+1], xr[4*q+2], xr[4*q+3]);
    } else {
        const float4* p = (const float4*)&g_xs[n * 16];
#pragma unroll
        for (int q = 0; q < 4; q++) { float4 v = p[q]; xs[4*q]=v.x; xs[4*q+1]=v.y; xs[4*q+2]=v.z; xs[4*q+3]=v.w; }
        const float4* pr = (const float4*)&g_xrot[n * 32];
#pragma unroll
        for (int q = 0; q < 8; q++) { float4 v = pr[q]; xr[4*q]=v.x; xr[4*q+1]=v.y; xr[4*q+2]=v.z; xr[4*q+3]=v.w; }
        float invd = g_nacc[n * 4];
#pragma unroll
        for (int j = 0; j < 16; j++) {
            float gt = g_gate[n * 16 + j] * invd;
            xr[2 * j]     += gt * g_aggR[n * 32 + 2 * j];
            xr[2 * j + 1] += gt * g_aggR[n * 32 + 2 * j + 1];
        }
#pragma unroll
        for (int i = 0; i < 16; i++) xs[i] += g_aggS[n * 16 + i] * invd;
        float4* po = (float4*)&g_xs[n * 16];
#pragma unroll
        for (int q = 0; q < 4; q++) po[q] = make_float4(xs[4*q], xs[4*q+1], xs[4*q+2], xs[4*q+3]);
        float4* pw = (float4*)&g_xrot[n * 32];
#pragma unroll
        for (int q = 0; q < 8; q++) pw[q] = make_float4(xr[4*q], xr[4*q+1], xr[4*q+2], xr[4*q+3]);
    }

    // y = Wmix @ x_rot  (packed, vectorized weight loads)
    ull xr2[16];
#pragma unroll
    for (int j = 0; j < 16; j++) xr2[j] = pk2(xr[2 * j], xr[2 * j + 1]);
    ull* yo2 = (ull*)&g_y[n * 32];
#pragma unroll
    for (int i = 0; i < 16; i++) {
        ull acc = 0ull;
        const ulonglong2* wm = (const ulonglong2*)(sMix2 + i * 16);
#pragma unroll
        for (int j = 0; j < 8; j++) {
            ulonglong2 wp = wm[j];
            acc = fma2(wp.x, xr2[2 * j], acc);
            acc = fma2(wp.y, xr2[2 * j + 1], acc);
        }
        yo2[i] = acc;
    }
    ull gt2[8], as2[8];
#pragma unroll
    for (int i = 0; i < 8; i++) { gt2[i] = sbg2[i]; as2[i] = 0ull; }
#pragma unroll
    for (int k = 0; k < 16; k++) {
        ull xv2 = pk2(xs[k], xs[k]);
        const ulonglong2* wg = (const ulonglong2*)(sGate2 + k * 8);
        const ulonglong2* ws = (const ulonglong2*)(sWs2 + k * 8);
#pragma unroll
        for (int i = 0; i < 4; i++) {
            ulonglong2 wgp = wg[i], wsp = ws[i];
            gt2[2 * i]     = fma2(xv2, wgp.x, gt2[2 * i]);
            gt2[2 * i + 1] = fma2(xv2, wgp.y, gt2[2 * i + 1]);
            as2[2 * i]     = fma2(xv2, wsp.x, as2[2 * i]);
            as2[2 * i + 1] = fma2(xv2, wsp.y, as2[2 * i + 1]);
        }
    }
#pragma unroll
    for (int i = 0; i < 8; i++) {
        float2 gv = upk(gt2[i]);
        g_gate[n * 16 + 2 * i]     = 1.f / (1.f + __expf(-gv.x));
        g_gate[n * 16 + 2 * i + 1] = 1.f / (1.f + __expf(-gv.y));
        ((ull*)&g_as[n * 16])[i] = as2[i];
    }
    // zero accumulators for this layer's edge pass
    float4 z = make_float4(0.f, 0.f, 0.f, 0.f);
    float4* ar = (float4*)&g_aggR[n * 32];
#pragma unroll
    for (int q = 0; q < 8; q++) ar[q] = z;
    float4* as4 = (float4*)&g_aggS[n * 16];
#pragma unroll
    for (int q = 0; q < 4; q++) as4[q] = z;
}

// ---- per-edge layer (hot): warp = 32 CSR edges; prefetched coalesced gathers ----
__global__ void __launch_bounds__(128) kEdgeLayerC(
                           const float* __restrict__ Wg, const float* __restrict__ bg,
                           const float* __restrict__ Ws1, const float* __restrict__ bs1,
                           int layer) {
    __shared__ __align__(16) ull sWg2[128], sWs2[128];
    __shared__ ull sbg2[8], sbs2[8];
    __shared__ float smG[4][32 * SLOT];
    __shared__ int scol[4][32], srow[4][32];
    for (int t = threadIdx.x; t < 128; t += blockDim.x) {
        sWg2[t] = ((const ull*)(Wg + layer * 256))[t];
        sWs2[t] = ((const ull*)(Ws1 + layer * 512 + 256))[t];
    }
    if (threadIdx.x < 8) {
        sbg2[threadIdx.x] = ((const ull*)(bg + layer * 16))[threadIdx.x];
        sbs2[threadIdx.x] = ((const ull*)(bs1 + layer * 16))[threadIdx.x];
    }
    __syncthreads();
    int w = threadIdx.x >> 5;
    int lane = threadIdx.x & 31;
    int p = blockIdx.x * 128 + threadIdx.x;   // NE % 128 == 0

    // ---- phase 1: edge-parallel g/bs into smem (vectorized weight loads) ----
    {
        float4 rec = g_rec[p];
        scol[w][lane] = __float_as_int(rec.x);
        srow[w][lane] = g_erow[p];
        float s1p = rec.y, c1 = rec.z, t1 = rec.w;
        float emb[16];
        emb[0] = s1p;
        float sk = s1p, ck = c1;
#pragma unroll
        for (int k = 1; k < 16; k++) {
            float sn = fmaf(sk, c1,  ck * s1p);
            float cn = fmaf(ck, c1, -sk * t1);
            emb[k] = sn; sk = sn; ck = cn;
        }
        ull g2[8], b2[8];
#pragma unroll
        for (int i = 0; i < 8; i++) { g2[i] = sbg2[i]; b2[i] = sbs2[i]; }
#pragma unroll
        for (int k = 0; k < 16; k++) {
            ull dv2 = pk2(emb[k], emb[k]);
            const ulonglong2* wg = (const ulonglong2*)(sWg2 + k * 8);
            const ulonglong2* ws = (const ulonglong2*)(sWs2 + k * 8);
#pragma unroll
            for (int i = 0; i < 4; i++) {
                ulonglong2 wgp = wg[i], wsp = ws[i];
                g2[2 * i]     = fma2(dv2, wgp.x, g2[2 * i]);
                g2[2 * i + 1] = fma2(dv2, wgp.y, g2[2 * i + 1]);
                b2[2 * i]     = fma2(dv2, wsp.x, b2[2 * i]);
                b2[2 * i + 1] = fma2(dv2, wsp.y, b2[2 * i + 1]);
            }
        }
        float* slot = &smG[w][lane * SLOT];
#pragma unroll
        for (int i = 0; i < 8; i++) {
            float2 gv = upk(g2[i]);
            slot[2 * i]     = gv.x;
            slot[2 * i + 1] = gv.y;
            float2 bv = upk(b2[i]);
            slot[16 + 2 * i]     = bv.x;
            slot[16 + 2 * i + 1] = bv.y;
        }
    }
    __syncwarp();

    // ---- phase 2: two 16-edge batches; branch-free prefetch then ALU accumulate ----
    const float* smw = smG[w];
    const int* colw = scol[w];
    const int* roww = srow[w];
    int gidx = lane >> 1;
    bool sl = (lane < 16);
    float accR = 0.f, accS = 0.f;
    int cur = roww[0];
#pragma unroll
    for (int half = 0; half < 2; half++) {
        int base = half * 16;
        float yv[16], av[16];
#pragma unroll
        for (int e = 0; e < 16; e++) {
            int c = colw[base + e];
            yv[e] = g_y[(size_t)c * 32 + lane];
            av[e] = sl ? g_as[(size_t)c * 16 + lane] : 0.f;
        }
#pragma unroll
        for (int e = 0; e < 16; e++) {
            int idx = base + e;
            int r = roww[idx];
            if (r != cur) {
                red1(&g_aggR[(size_t)cur * 32 + lane], accR);
                if (sl) red1(&g_aggS[(size_t)cur * 16 + lane], accS);
                accR = 0.f; accS = 0.f; cur = r;
            }
            float gv = smw[idx * SLOT + gidx];
            accR = fmaf(gv, yv[e], accR);
            if (sl) accS += lrelu(av[e] + smw[idx * SLOT + 16 + lane]);
        }
    }
    red1(&g_aggR[(size_t)cur * 32 + lane], accR);
    if (sl) red1(&g_aggS[(size_t)cur * 16 + lane], accS);
}

// ---- readout: final post + rotate out + 48->144->6 MLP (f32x2) + graph scatter ----
__global__ void __launch_bounds__(256) kOut(
                     const float* __restrict__ W1, const float* __restrict__ b1,
                     const float* __restrict__ W2, const float* __restrict__ b2,
                     const int* __restrict__ batch, float* __restrict__ out) {
    __shared__ __align__(16) float sW1[48 * 144];
    __shared__ __align__(16) float sW2[144 * 6];
    __shared__ __align__(16) float sb1[144];
    __shared__ float sb2[8];
    for (int t = threadIdx.x; t < 48 * 144; t += blockDim.x) sW1[t] = W1[t];
    for (int t = threadIdx.x; t < 144 * 6; t += blockDim.x) sW2[t] = W2[t];
    for (int t = threadIdx.x; t < 144; t += blockDim.x) sb1[t] = b1[t];
    if (threadIdx.x < 6) sb2[threadIdx.x] = b2[threadIdx.x];
    if (threadIdx.x >= 6 && threadIdx.x < 8) sb2[threadIdx.x] = 0.f;
    __syncthreads();
    int n = blockIdx.x * blockDim.x + threadIdx.x;
    if (n >= NN) return;
    float invd = g_nacc[n * 4];
    float xc[48];
#pragma unroll
    for (int i = 0; i < 16; i++)
        xc[i] = g_xs[n * 16 + i] + g_aggS[n * 16 + i] * invd;
    float cc = g_ncs[2 * n], ss = g_ncs[2 * n + 1];
#pragma unroll
    for (int j = 0; j < 16; j++) {
        float gt = g_gate[n * 16 + j] * invd;
        float x0 = g_xrot[n * 32 + 2 * j]     + gt * g_aggR[n * 32 + 2 * j];
        float x1 = g_xrot[n * 32 + 2 * j + 1] + gt * g_aggR[n * 32 + 2 * j + 1];
        xc[16 + 2 * j]     = cc * x0 - ss * x1;
        xc[16 + 2 * j + 1] = ss * x0 + cc * x1;
    }
    ull u2[3];
    u2[0] = pk2(sb2[0], sb2[1]);
    u2[1] = pk2(sb2[2], sb2[3]);
    u2[2] = pk2(sb2[4], sb2[5]);
    for (int o = 0; o < 144; o += 4) {
        const ull* wb = (const ull*)&sb1[o];
        ull h01 = wb[0], h23 = wb[1];
#pragma unroll
        for (int k = 0; k < 48; k++) {
            const ull* wp = (const ull*)&sW1[k * 144 + o];
            ull xv2 = pk2(xc[k], xc[k]);
            h01 = fma2(xv2, wp[0], h01);
            h23 = fma2(xv2, wp[1], h23);
        }
        float2 ha = upk(h01), hb = upk(h23);
        float hv[4] = {lrelu(ha.x), lrelu(ha.y), lrelu(hb.x), lrelu(hb.y)};
#pragma unroll
        for (int j = 0; j < 4; j++) {
            ull hj2 = pk2(hv[j], hv[j]);
            const ull* w2p = (const ull*)&sW2[(o + j) * 6];
            u2[0] = fma2(hj2, w2p[0], u2[0]);
            u2[1] = fma2(hj2, w2p[1], u2[1]);
            u2[2] = fma2(hj2, w2p[2], u2[2]);
        }
    }
    int b = batch[n];
    float2 ua = upk(u2[0]), ub = upk(u2[1]), uc = upk(u2[2]);
    atomicAdd(&out[b * 6 + 0], ua.x);
    atomicAdd(&out[b * 6 + 1], ua.y);
    atomicAdd(&out[b * 6 + 2], ub.x);
    atomicAdd(&out[b * 6 + 3], ub.y);
    atomicAdd(&out[b * 6 + 4], uc.x);
    atomicAdd(&out[b * 6 + 5], uc.y);
}

extern "C" void kernel_launch(void* const* d_in, const int* in_sizes, int n_in,
                              void* d_out, int out_size) {
    const float* pos   = (const float*)d_in[0];
    const float* Wemb  = (const float*)d_in[1];
    const float* wse   = (const float*)d_in[2];
    const float* bse   = (const float*)d_in[3];
    const float* Wg    = (const float*)d_in[4];
    const float* bg    = (const float*)d_in[5];
    const float* Wmix  = (const float*)d_in[6];
    const float* Wgate = (const float*)d_in[7];
    const float* bgate = (const float*)d_in[8];
    const float* Ws1   = (const float*)d_in[9];
    const float* bs1   = (const float*)d_in[10];
    const float* W1    = (const float*)d_in[11];
    const float* b1    = (const float*)d_in[12];
    const float* W2    = (const float*)d_in[13];
    const float* b2    = (const float*)d_in[14];
    const int*   ei    = (const int*)d_in[15];
    const int*   batch = (const int*)d_in[16];
    float* out = (float*)d_out;

    int nb = (NN + 255) / 256;
    int eb = (NE + 255) / 256;

    kZero<<<1563, 256>>>(out);
    kGraphAcc<<<eb, 256>>>(pos, batch, ei);
    kCenterScan<<<NBLK, 256>>>(pos, batch);
    kScanB<<<1, 512>>>();
    kScanC<<<NBLK, 256>>>();
    kEdgeFill<<<eb, 256>>>(ei);
    for (int l = 0; l < 3; l++) {
        kNodeFuse<<<nb, 256>>>(wse, bse, Wemb, Wmix, Wgate, bgate, Ws1, l);
        kEdgeLayerC<<<NE / 128, 128>>>(Wg, bg, Ws1, bs1, l);
    }
    kOut<<<nb, 256>>>(W1, b1, W2, b2, batch, out);
}